// round 9
// baseline (speedup 1.0000x reference)
#include <cuda_runtime.h>
#include <cuda_bf16.h>
#include <mma.h>
#include <math.h>
#include <stdint.h>

using namespace nvcuda;

#define NN 50000
#define NP 50048            // padded rows: 391 * 128
#define DD 128
#define HH 4
#define CC 32
#define LL 3
#define EE 800000
#define SLOPE 0.2f
#define BN_EPS 1e-5
#define BN_BLKS 400
#define ACONV_G ((NP * 32) / 256)    // 6256

// ---------------- scratch (static device globals; no allocation) ----------------
__device__ float g_xl[NP * DD];
__device__ float g_xr[NP * DD];
__device__ float g_xres[NP * DD];
__device__ float g_h[NP * DD];
__device__ __nv_bfloat16 g_ah[NP * DD];      // A hi split (bf16)
__device__ __nv_bfloat16 g_al[NP * DD];      // A lo split
__device__ __nv_bfloat16 g_wh[3 * DD * DD];  // W hi split (up to 3 mats)
__device__ __nv_bfloat16 g_wl[3 * DD * DD];
__device__ int   g_rowptr[NN + 1];
__device__ int   g_cursor[NN];
__device__ int   g_cnt[NN];
__device__ int   g_col[EE];
__device__ int   g_bsum[128];
__device__ int   g_boff[128];
__device__ float g_psum[BN_BLKS * DD];
__device__ float g_psq[BN_BLKS * DD];
__device__ float g_bnsc[DD];
__device__ float g_bnsh[DD];
__device__ int   g_is64;

__device__ __forceinline__ uint32_t pack_bf2(__nv_bfloat16 a, __nv_bfloat16 b) {
    __nv_bfloat162 p;
    p.x = a; p.y = b;
    return *(uint32_t*)&p;
}

__device__ __forceinline__ void cp16(uint32_t s, const void* g) {
    asm volatile("cp.async.cg.shared.global [%0], [%1], 16;" :: "r"(s), "l"(g));
}

// ---------------- edge_index dtype detection ----------------
__global__ void detect_dtype_k(const unsigned int* __restrict__ w) {
    if (threadIdx.x == 0 && blockIdx.x == 0) {
        int is64 = 1;
        for (int i = 1; i < 64; i += 2)
            if (w[i] != 0u) { is64 = 0; break; }
        g_is64 = is64;
    }
}

__device__ __forceinline__ int edge_val(const void* ei, long long idx) {
    if (g_is64) return (int)((const long long*)ei)[idx];
    return ((const int*)ei)[idx];
}

// ---------------- CSR build ----------------
__global__ void zero_cnt_k() {
    int i = blockIdx.x * blockDim.x + threadIdx.x;
    if (i < NN) g_cnt[i] = 0;
}

__global__ void count_k(const void* __restrict__ ei, int E) {
    int e = blockIdx.x * blockDim.x + threadIdx.x;
    if (e < E) {
        int dst = edge_val(ei, (long long)E + e);
        atomicAdd(&g_cnt[dst], 1);
    }
}

__global__ void scan1_k() {
    __shared__ int red[512];
    int t = threadIdx.x;
    int i = blockIdx.x * 512 + t;
    red[t] = (i < NN) ? g_cnt[i] : 0;
    __syncthreads();
    for (int off = 256; off > 0; off >>= 1) {
        if (t < off) red[t] += red[t + off];
        __syncthreads();
    }
    if (t == 0) g_bsum[blockIdx.x] = red[0];
}

__global__ void scan2_k(int nb) {
    __shared__ int s[128];
    int t = threadIdx.x;
    int own = (t < nb) ? g_bsum[t] : 0;
    s[t] = own;
    __syncthreads();
    for (int off = 1; off < 128; off <<= 1) {
        int v = (t >= off) ? s[t - off] : 0;
        __syncthreads();
        s[t] += v;
        __syncthreads();
    }
    if (t < nb) g_boff[t] = s[t] - own;
}

__global__ void scan3_k() {
    __shared__ int s[512];
    int t = threadIdx.x;
    int i = blockIdx.x * 512 + t;
    int own = (i < NN) ? g_cnt[i] : 0;
    s[t] = own;
    __syncthreads();
    for (int off = 1; off < 512; off <<= 1) {
        int v = (t >= off) ? s[t - off] : 0;
        __syncthreads();
        s[t] += v;
        __syncthreads();
    }
    int boff = g_boff[blockIdx.x];
    if (i < NN) {
        int excl = s[t] - own + boff;
        g_rowptr[i] = excl;
        g_cursor[i] = excl;
        if (i == NN - 1) g_rowptr[NN] = s[t] + boff;
    }
}

__global__ void fill_k(const void* __restrict__ ei, int E) {
    int e = blockIdx.x * blockDim.x + threadIdx.x;
    if (e < E) {
        int dst = edge_val(ei, (long long)E + e);
        int src = edge_val(ei, e);
        int pos = atomicAdd(&g_cursor[dst], 1);
        g_col[pos] = src;
    }
}

// ---------------- fused A + W conversion ----------------
// blocks [0, ACONV_G): X -> (BN affine + leaky) -> bf16 hi/lo split
// blocks [ACONV_G, +16*nmats): W -> bf16 hi/lo split
__global__ void aconvw_k(const float* __restrict__ X,
                         const float* __restrict__ W0, const float* __restrict__ W1,
                         const float* __restrict__ W2, int bnmode)
{
    int b = blockIdx.x;
    if (b < ACONV_G) {
        int i = b * 256 + threadIdx.x;       // float4 id
        int row = i >> 5;
        int c = (i & 31) * 4;
        float4 v = make_float4(0.f, 0.f, 0.f, 0.f);
        if (row < NN) v = ((const float4*)X)[i];
        float vv[4] = {v.x, v.y, v.z, v.w};
        __nv_bfloat16 hb[4], lb[4];
#pragma unroll
        for (int j = 0; j < 4; j++) {
            float x = vv[j];
            if (bnmode) {
                x = fmaf(x, g_bnsc[c + j], g_bnsh[c + j]);
                x = (x > 0.f) ? x : SLOPE * x;
            }
            hb[j] = __float2bfloat16(x);
            lb[j] = __float2bfloat16(x - __bfloat162float(hb[j]));
        }
        uint2 ph, pl;
        ph.x = pack_bf2(hb[0], hb[1]); ph.y = pack_bf2(hb[2], hb[3]);
        pl.x = pack_bf2(lb[0], lb[1]); pl.y = pack_bf2(lb[2], lb[3]);
        ((uint2*)g_ah)[i] = ph;
        ((uint2*)g_al)[i] = pl;
    } else {
        int wb = b - ACONV_G;
        int m = wb >> 4;                     // 16 blocks per matrix
        const float* W = (m == 0) ? W0 : (m == 1) ? W1 : W2;
        if (W == nullptr) return;
        int q = (wb & 15) * 256 + threadIdx.x;   // float4 id 0..4095
        float4 v = ((const float4*)W)[q];
        float vv[4] = {v.x, v.y, v.z, v.w};
        __nv_bfloat16 hb[4], lb[4];
#pragma unroll
        for (int j = 0; j < 4; j++) {
            float x = vv[j];
            hb[j] = __float2bfloat16(x);
            lb[j] = __float2bfloat16(x - __bfloat162float(hb[j]));
        }
        uint2 ph, pl;
        ph.x = pack_bf2(hb[0], hb[1]); ph.y = pack_bf2(hb[2], hb[3]);
        pl.x = pack_bf2(lb[0], lb[1]); pl.y = pack_bf2(lb[2], lb[3]);
        ((uint2*)g_wh)[m * 4096 + q] = ph;
        ((uint2*)g_wl)[m * 4096 + q] = pl;
    }
}

// ---------------- cp.async double-buffered bf16x3 WMMA triple GEMM ----------------
// C[M,128] = A[M,128] @ W[128,128]; 3 terms Ah*Bh + Al*Bh + Ah*Bl, fp32 accum.
// 4 K-chunks of 32, 2 smem buffers, LDGSTS pipeline (prefetch c+2 during MMA of c).
#define AS 40                      // A smem stride (elements)
#define BS 136                     // B smem stride
#define ABY (128 * AS * 2)         // 10240 bytes per A term
#define BBY (32 * BS * 2)          // 8704 bytes per B term
#define BUFBY (2 * ABY + 2 * BBY)  // 37888 bytes per buffer
#define SMSZ (2 * BUFBY)           // 75776

__global__ void __launch_bounds__(256, 2) gemm_k(
    float* __restrict__ O0, float* __restrict__ O1, float* __restrict__ O2)
{
    extern __shared__ char smem[];
    int t = threadIdx.x;
    int wid = t >> 5;
    int wm = wid >> 1;   // 0..3
    int wn = wid & 1;    // 0..1
    int row0 = blockIdx.y * 128;
    int mat = blockIdx.x;
    float* O = (mat == 0) ? O0 : (mat == 1) ? O1 : O2;
    const __nv_bfloat16* Wh = g_wh + (size_t)mat * DD * DD;
    const __nv_bfloat16* Wl_ = g_wl + (size_t)mat * DD * DD;

    uint32_t sbase = (uint32_t)__cvta_generic_to_shared(smem);

    // per-thread cp.async source indices
    int a_r0 = t >> 2;                 // A line 0 row (g=0)
    int a_c0 = (t & 3) * 8;
    int b_r0 = t >> 4;                 // B line 0 row
    int b_c0 = (t & 15) * 8;

#define PREFETCH(K0, BUF) do { \
        uint32_t sb_ = sbase + (BUF) * BUFBY; \
        _Pragma("unroll") \
        for (int g_ = 0; g_ < 2; g_++) { \
            int r_ = a_r0 + g_ * 64; \
            size_t go_ = (size_t)(row0 + r_) * 128 + (K0) + a_c0; \
            uint32_t so_ = (uint32_t)(r_ * AS + a_c0) * 2; \
            cp16(sb_ + so_, g_ah + go_); \
            cp16(sb_ + ABY + so_, g_al + go_); \
        } \
        _Pragma("unroll") \
        for (int g_ = 0; g_ < 2; g_++) { \
            int r_ = b_r0 + g_ * 16; \
            size_t go_ = (size_t)((K0) + r_) * 128 + b_c0; \
            uint32_t so_ = (uint32_t)(r_ * BS + b_c0) * 2; \
            cp16(sb_ + 2 * ABY + so_, Wh + go_); \
            cp16(sb_ + 2 * ABY + BBY + so_, Wl_ + go_); \
        } \
        asm volatile("cp.async.commit_group;" ::: "memory"); \
    } while (0)

    wmma::fragment<wmma::accumulator, 16, 16, 16, float> acc[2][4];
#pragma unroll
    for (int i = 0; i < 2; i++)
#pragma unroll
        for (int j = 0; j < 4; j++) wmma::fill_fragment(acc[i][j], 0.0f);

    PREFETCH(0, 0);
    PREFETCH(32, 1);

#pragma unroll
    for (int c = 0; c < 4; c++) {
        if (c == 3)
            asm volatile("cp.async.wait_group 0;" ::: "memory");
        else
            asm volatile("cp.async.wait_group 1;" ::: "memory");
        __syncthreads();

        char* buf = smem + (c & 1) * BUFBY;
        __nv_bfloat16* sAh = (__nv_bfloat16*)buf;
        __nv_bfloat16* sAl = (__nv_bfloat16*)(buf + ABY);
        __nv_bfloat16* sBh = (__nv_bfloat16*)(buf + 2 * ABY);
        __nv_bfloat16* sBl = (__nv_bfloat16*)(buf + 2 * ABY + BBY);

#pragma unroll
        for (int kk = 0; kk < 32; kk += 16) {
            wmma::fragment<wmma::matrix_a, 16, 16, 16, __nv_bfloat16, wmma::row_major> ah[2], al[2];
#pragma unroll
            for (int m2 = 0; m2 < 2; m2++) {
                wmma::load_matrix_sync(ah[m2], &sAh[(wm * 32 + m2 * 16) * AS + kk], AS);
                wmma::load_matrix_sync(al[m2], &sAl[(wm * 32 + m2 * 16) * AS + kk], AS);
            }
#pragma unroll
            for (int n = 0; n < 4; n++) {
                wmma::fragment<wmma::matrix_b, 16, 16, 16, __nv_bfloat16, wmma::row_major> bh, bl;
                wmma::load_matrix_sync(bh, &sBh[kk * BS + wn * 64 + n * 16], BS);
                wmma::load_matrix_sync(bl, &sBl[kk * BS + wn * 64 + n * 16], BS);
#pragma unroll
                for (int m2 = 0; m2 < 2; m2++) {
                    wmma::mma_sync(acc[m2][n], ah[m2], bh, acc[m2][n]);
                    wmma::mma_sync(acc[m2][n], ah[m2], bl, acc[m2][n]);
                    wmma::mma_sync(acc[m2][n], al[m2], bh, acc[m2][n]);
                }
            }
        }
        __syncthreads();
        if (c < 2) PREFETCH((c + 2) * 32, c & 1);
    }
#undef PREFETCH

#pragma unroll
    for (int m2 = 0; m2 < 2; m2++)
#pragma unroll
        for (int n = 0; n < 4; n++) {
            int gr = row0 + wm * 32 + m2 * 16;
            int gc = wn * 64 + n * 16;
            wmma::store_matrix_sync(&O[(size_t)gr * 128 + gc], acc[m2][n], 128, wmma::mem_row_major);
        }
}

// ---------------- fused GATv2: warp per node, float4 per lane ----------------
__global__ void __launch_bounds__(256) gat_warp_k(
    const float* __restrict__ xl, const float* __restrict__ xr,
    const float* __restrict__ xres, const float* __restrict__ bias,
    const float* __restrict__ att, float* __restrict__ out)
{
    int warp = threadIdx.x >> 5;
    int lane = threadIdx.x & 31;
    int v = blockIdx.x * 8 + warp;          // 6250 * 8 == 50000, exact
    int c4 = lane * 4;

    float4 xrv = *(const float4*)&xr[(size_t)v * DD + c4];
    float4 a4  = *(const float4*)&att[c4];

    float denom = 0.f;
    float4 acc = make_float4(0.f, 0.f, 0.f, 0.f);

#define GAT_EDGE(SRC) do { \
        float4 m = *(const float4*)&xl[(size_t)(SRC) * DD + c4]; \
        float p0 = m.x + xrv.x; p0 = (p0 > 0.f) ? p0 : SLOPE * p0; \
        float p1 = m.y + xrv.y; p1 = (p1 > 0.f) ? p1 : SLOPE * p1; \
        float p2 = m.z + xrv.z; p2 = (p2 > 0.f) ? p2 : SLOPE * p2; \
        float p3 = m.w + xrv.w; p3 = (p3 > 0.f) ? p3 : SLOPE * p3; \
        float part = fmaf(p0, a4.x, fmaf(p1, a4.y, fmaf(p2, a4.z, p3 * a4.w))); \
        part += __shfl_xor_sync(0xffffffffu, part, 1); \
        part += __shfl_xor_sync(0xffffffffu, part, 2); \
        part += __shfl_xor_sync(0xffffffffu, part, 4); \
        float w = __expf(part); \
        denom += w; \
        acc.x = fmaf(w, m.x, acc.x); \
        acc.y = fmaf(w, m.y, acc.y); \
        acc.z = fmaf(w, m.z, acc.z); \
        acc.w = fmaf(w, m.w, acc.w); \
    } while (0)

    GAT_EDGE(v);   // self loop

    int j = g_rowptr[v];
    int e2 = g_rowptr[v + 1];
    for (; j + 2 <= e2; j += 2) {
        int s0 = g_col[j];
        int s1 = g_col[j + 1];
        GAT_EDGE(s0);
        GAT_EDGE(s1);
    }
    if (j < e2) {
        int s0 = g_col[j];
        GAT_EDGE(s0);
    }
#undef GAT_EDGE

    float inv = 1.f / denom;
    float4 b4 = *(const float4*)&bias[c4];
    float4 r4 = *(const float4*)&xres[(size_t)v * DD + c4];
    float4 o;
    o.x = fmaf(acc.x, inv, b4.x + r4.x);
    o.y = fmaf(acc.y, inv, b4.y + r4.y);
    o.z = fmaf(acc.z, inv, b4.z + r4.z);
    o.w = fmaf(acc.w, inv, b4.w + r4.w);
    *(float4*)&out[(size_t)v * DD + c4] = o;
}

// ---------------- BatchNorm: per-block fp32 partials, then reduce ----------------
__global__ void bn_stats_k(const float* __restrict__ x) {
    int t = threadIdx.x;
    int rows = (NN + gridDim.x - 1) / gridDim.x;
    int r0 = blockIdx.x * rows;
    int r1 = min(NN, r0 + rows);
    float s = 0.f, ss = 0.f;
    for (int r = r0; r < r1; r++) {
        float v = x[(size_t)r * DD + t];
        s += v;
        ss = fmaf(v, v, ss);
    }
    g_psum[blockIdx.x * DD + t] = s;
    g_psq[blockIdx.x * DD + t] = ss;
}

__global__ void bn_final_k(const float* __restrict__ gamma, const float* __restrict__ beta) {
    int t = threadIdx.x;
    double s = 0.0, ss = 0.0;
    for (int b = 0; b < BN_BLKS; b++) {
        s += (double)g_psum[b * DD + t];
        ss += (double)g_psq[b * DD + t];
    }
    double mu = s / (double)NN;
    double var = ss / (double)NN - mu * mu;
    float sc = (float)(1.0 / sqrt(var + BN_EPS)) * gamma[t];
    g_bnsc[t] = sc;
    g_bnsh[t] = beta[t] - (float)mu * sc;
}

// ---------------- final bias add + copy to output ----------------
__global__ void bias_copy_k(const float* __restrict__ in, const float* __restrict__ bias,
                            float* __restrict__ out)
{
    int i = blockIdx.x * blockDim.x + threadIdx.x;
    if (i < NN * 32) {
        float4 v = ((const float4*)in)[i];
        int c = (i & 31) * 4;
        v.x += bias[c + 0];
        v.y += bias[c + 1];
        v.z += bias[c + 2];
        v.w += bias[c + 3];
        ((float4*)out)[i] = v;
    }
}

// ---------------- launch ----------------
extern "C" void kernel_launch(void* const* d_in, const int* in_sizes, int n_in,
                              void* d_out, int out_size)
{
    const float* x     = (const float*)d_in[0];
    const void*  ei    = (const void*)d_in[1];
    const float* Wl    = (const float*)d_in[2];
    const float* Wr    = (const float*)d_in[3];
    const float* att   = (const float*)d_in[4];
    const float* bias  = (const float*)d_in[5];
    const float* Wres  = (const float*)d_in[6];
    const float* gamma = (const float*)d_in[7];
    const float* beta  = (const float*)d_in[8];
    const float* Wout  = (const float*)d_in[9];
    const float* bout  = (const float*)d_in[10];
    float* out = (float*)d_out;

    int E = in_sizes[1] / 2;

    float *xl, *xr, *xres, *h;
    cudaGetSymbolAddress((void**)&xl,   g_xl);
    cudaGetSymbolAddress((void**)&xr,   g_xr);
    cudaGetSymbolAddress((void**)&xres, g_xres);
    cudaGetSymbolAddress((void**)&h,    g_h);

    cudaFuncSetAttribute(gemm_k, cudaFuncAttributeMaxDynamicSharedMemorySize, SMSZ);

    dim3 gg3(3, NP / 128);   // (3, 391)
    dim3 gg1(1, NP / 128);

    // order: gemm_k is the 4th launch (ncu capture window)
    detect_dtype_k<<<1, 32>>>((const unsigned int*)ei);
    zero_cnt_k<<<(NN + 255) / 256, 256>>>();
    aconvw_k<<<ACONV_G + 48, 256>>>(x, Wl, Wr, Wres, 0);
    gemm_k<<<gg3, 256, SMSZ>>>(xl, xr, xres);

    // CSR build
    count_k<<<(E + 255) / 256, 256>>>(ei, E);
    int nb = (NN + 511) / 512;
    scan1_k<<<nb, 512>>>();
    scan2_k<<<1, 128>>>(nb);
    scan3_k<<<nb, 512>>>();
    fill_k<<<(E + 255) / 256, 256>>>(ei, E);

    for (int i = 0; i < LL; i++) {
        if (i > 0) {
            aconvw_k<<<ACONV_G + 48, 256>>>(h, Wl + (size_t)i * DD * DD,
                                            Wr + (size_t)i * DD * DD,
                                            Wres + (size_t)i * DD * DD, 1);
            gemm_k<<<gg3, 256, SMSZ>>>(xl, xr, xres);
        }
        gat_warp_k<<<NN / 8, 256>>>(xl, xr, xres, bias + (size_t)i * DD,
                                    att + (size_t)i * HH * CC, h);
        bn_stats_k<<<BN_BLKS, DD>>>(h);
        bn_final_k<<<1, DD>>>(gamma + (size_t)i * DD, beta + (size_t)i * DD);
    }

    // final linear
    aconvw_k<<<ACONV_G + 16, 256>>>(h, Wout, nullptr, nullptr, 1);
    gemm_k<<<gg1, 256, SMSZ>>>(xl, nullptr, nullptr);
    bias_copy_k<<<(NN * 32 + 255) / 256, 256>>>(xl, bout, out);
}

// round 10
// speedup vs baseline: 1.0097x; 1.0097x over previous
#include <cuda_runtime.h>
#include <cuda_bf16.h>
#include <mma.h>
#include <math.h>
#include <stdint.h>

using namespace nvcuda;

#define NN 50000
#define NP 50048            // padded rows: 391 * 128
#define DD 128
#define HH 4
#define CC 32
#define LL 3
#define EE 800000
#define SLOPE 0.2f
#define BN_EPS 1e-5
#define BN_BLKS 400
#define ACONV_G ((NP * 32) / 256)    // 6256

// ---------------- scratch (static device globals; no allocation) ----------------
__device__ float g_xl[NP * DD];
__device__ float g_xr[NP * DD];
__device__ float g_xres[NP * DD];
__device__ float g_h[NP * DD];
__device__ __nv_bfloat16 g_ah[NP * DD];      // A hi split (bf16)
__device__ __nv_bfloat16 g_al[NP * DD];      // A lo split
__device__ __nv_bfloat16 g_wh[3 * DD * DD];  // W hi split (up to 3 mats)
__device__ __nv_bfloat16 g_wl[3 * DD * DD];
__device__ int   g_rowptr[NN + 1];
__device__ int   g_cursor[NN];
__device__ int   g_cnt[NN];
__device__ int   g_col[EE];
__device__ int   g_bsum[128];
__device__ int   g_boff[128];
__device__ float g_psum[BN_BLKS * DD];
__device__ float g_psq[BN_BLKS * DD];
__device__ float g_bnsc[DD];
__device__ float g_bnsh[DD];
__device__ int   g_is64;

__device__ __forceinline__ uint32_t pack_bf2(__nv_bfloat16 a, __nv_bfloat16 b) {
    __nv_bfloat162 p;
    p.x = a; p.y = b;
    return *(uint32_t*)&p;
}

__device__ __forceinline__ void cp16(uint32_t s, const void* g) {
    asm volatile("cp.async.cg.shared.global [%0], [%1], 16;" :: "r"(s), "l"(g));
}

// ---------------- edge_index dtype detection ----------------
__global__ void detect_dtype_k(const unsigned int* __restrict__ w) {
    if (threadIdx.x == 0 && blockIdx.x == 0) {
        int is64 = 1;
        for (int i = 1; i < 64; i += 2)
            if (w[i] != 0u) { is64 = 0; break; }
        g_is64 = is64;
    }
}

__device__ __forceinline__ int edge_val(const void* ei, long long idx) {
    if (g_is64) return (int)((const long long*)ei)[idx];
    return ((const int*)ei)[idx];
}

// ---------------- CSR build ----------------
__global__ void zero_cnt_k() {
    int i = blockIdx.x * blockDim.x + threadIdx.x;
    if (i < NN) g_cnt[i] = 0;
}

__global__ void count_k(const void* __restrict__ ei, int E) {
    int e = blockIdx.x * blockDim.x + threadIdx.x;
    if (e < E) {
        int dst = edge_val(ei, (long long)E + e);
        atomicAdd(&g_cnt[dst], 1);
    }
}

__global__ void scan1_k() {
    __shared__ int red[512];
    int t = threadIdx.x;
    int i = blockIdx.x * 512 + t;
    red[t] = (i < NN) ? g_cnt[i] : 0;
    __syncthreads();
    for (int off = 256; off > 0; off >>= 1) {
        if (t < off) red[t] += red[t + off];
        __syncthreads();
    }
    if (t == 0) g_bsum[blockIdx.x] = red[0];
}

__global__ void scan2_k(int nb) {
    __shared__ int s[128];
    int t = threadIdx.x;
    int own = (t < nb) ? g_bsum[t] : 0;
    s[t] = own;
    __syncthreads();
    for (int off = 1; off < 128; off <<= 1) {
        int v = (t >= off) ? s[t - off] : 0;
        __syncthreads();
        s[t] += v;
        __syncthreads();
    }
    if (t < nb) g_boff[t] = s[t] - own;
}

__global__ void scan3_k() {
    __shared__ int s[512];
    int t = threadIdx.x;
    int i = blockIdx.x * 512 + t;
    int own = (i < NN) ? g_cnt[i] : 0;
    s[t] = own;
    __syncthreads();
    for (int off = 1; off < 512; off <<= 1) {
        int v = (t >= off) ? s[t - off] : 0;
        __syncthreads();
        s[t] += v;
        __syncthreads();
    }
    int boff = g_boff[blockIdx.x];
    if (i < NN) {
        int excl = s[t] - own + boff;
        g_rowptr[i] = excl;
        g_cursor[i] = excl;
        if (i == NN - 1) g_rowptr[NN] = s[t] + boff;
    }
}

__global__ void fill_k(const void* __restrict__ ei, int E) {
    int e = blockIdx.x * blockDim.x + threadIdx.x;
    if (e < E) {
        int dst = edge_val(ei, (long long)E + e);
        int src = edge_val(ei, e);
        int pos = atomicAdd(&g_cursor[dst], 1);
        g_col[pos] = src;
    }
}

// ---------------- fused A + W conversion ----------------
__global__ void aconvw_k(const float* __restrict__ X,
                         const float* __restrict__ W0, const float* __restrict__ W1,
                         const float* __restrict__ W2, int bnmode)
{
    int b = blockIdx.x;
    if (b < ACONV_G) {
        int i = b * 256 + threadIdx.x;       // float4 id
        int row = i >> 5;
        int c = (i & 31) * 4;
        float4 v = make_float4(0.f, 0.f, 0.f, 0.f);
        if (row < NN) v = ((const float4*)X)[i];
        float vv[4] = {v.x, v.y, v.z, v.w};
        __nv_bfloat16 hb[4], lb[4];
#pragma unroll
        for (int j = 0; j < 4; j++) {
            float x = vv[j];
            if (bnmode) {
                x = fmaf(x, g_bnsc[c + j], g_bnsh[c + j]);
                x = (x > 0.f) ? x : SLOPE * x;
            }
            hb[j] = __float2bfloat16(x);
            lb[j] = __float2bfloat16(x - __bfloat162float(hb[j]));
        }
        uint2 ph, pl;
        ph.x = pack_bf2(hb[0], hb[1]); ph.y = pack_bf2(hb[2], hb[3]);
        pl.x = pack_bf2(lb[0], lb[1]); pl.y = pack_bf2(lb[2], lb[3]);
        ((uint2*)g_ah)[i] = ph;
        ((uint2*)g_al)[i] = pl;
    } else {
        int wb = b - ACONV_G;
        int m = wb >> 4;                     // 16 blocks per matrix
        const float* W = (m == 0) ? W0 : (m == 1) ? W1 : W2;
        if (W == nullptr) return;
        int q = (wb & 15) * 256 + threadIdx.x;   // float4 id 0..4095
        float4 v = ((const float4*)W)[q];
        float vv[4] = {v.x, v.y, v.z, v.w};
        __nv_bfloat16 hb[4], lb[4];
#pragma unroll
        for (int j = 0; j < 4; j++) {
            float x = vv[j];
            hb[j] = __float2bfloat16(x);
            lb[j] = __float2bfloat16(x - __bfloat162float(hb[j]));
        }
        uint2 ph, pl;
        ph.x = pack_bf2(hb[0], hb[1]); ph.y = pack_bf2(hb[2], hb[3]);
        pl.x = pack_bf2(lb[0], lb[1]); pl.y = pack_bf2(lb[2], lb[3]);
        ((uint2*)g_wh)[m * 4096 + q] = ph;
        ((uint2*)g_wl)[m * 4096 + q] = pl;
    }
}

// ---------------- cp.async double-buffered bf16x3 WMMA triple GEMM ----------------
// If bias != nullptr: epilogue goes through smem, adds per-column bias, and does
// row-guarded (< Mlimit) float4 stores (used for the final layer writing d_out).
#define AS 40                      // A smem stride (elements)
#define BS 136                     // B smem stride
#define ABY (128 * AS * 2)         // 10240 bytes per A term
#define BBY (32 * BS * 2)          // 8704 bytes per B term
#define BUFBY (2 * ABY + 2 * BBY)  // 37888 bytes per buffer
#define SMSZ (2 * BUFBY)           // 75776 (>= 64K epilogue buffer)

__global__ void __launch_bounds__(256, 2) gemm_k(
    float* __restrict__ O0, float* __restrict__ O1, float* __restrict__ O2,
    const float* __restrict__ bias, int Mlimit)
{
    extern __shared__ char smem[];
    int t = threadIdx.x;
    int wid = t >> 5;
    int wm = wid >> 1;   // 0..3
    int wn = wid & 1;    // 0..1
    int row0 = blockIdx.y * 128;
    int mat = blockIdx.x;
    float* O = (mat == 0) ? O0 : (mat == 1) ? O1 : O2;
    const __nv_bfloat16* Wh = g_wh + (size_t)mat * DD * DD;
    const __nv_bfloat16* Wl_ = g_wl + (size_t)mat * DD * DD;

    uint32_t sbase = (uint32_t)__cvta_generic_to_shared(smem);

    int a_r0 = t >> 2;                 // A line row
    int a_c0 = (t & 3) * 8;
    int b_r0 = t >> 4;                 // B line row
    int b_c0 = (t & 15) * 8;

#define PREFETCH(K0, BUF) do { \
        uint32_t sb_ = sbase + (BUF) * BUFBY; \
        _Pragma("unroll") \
        for (int g_ = 0; g_ < 2; g_++) { \
            int r_ = a_r0 + g_ * 64; \
            size_t go_ = (size_t)(row0 + r_) * 128 + (K0) + a_c0; \
            uint32_t so_ = (uint32_t)(r_ * AS + a_c0) * 2; \
            cp16(sb_ + so_, g_ah + go_); \
            cp16(sb_ + ABY + so_, g_al + go_); \
        } \
        _Pragma("unroll") \
        for (int g_ = 0; g_ < 2; g_++) { \
            int r_ = b_r0 + g_ * 16; \
            size_t go_ = (size_t)((K0) + r_) * 128 + b_c0; \
            uint32_t so_ = (uint32_t)(r_ * BS + b_c0) * 2; \
            cp16(sb_ + 2 * ABY + so_, Wh + go_); \
            cp16(sb_ + 2 * ABY + BBY + so_, Wl_ + go_); \
        } \
        asm volatile("cp.async.commit_group;" ::: "memory"); \
    } while (0)

    wmma::fragment<wmma::accumulator, 16, 16, 16, float> acc[2][4];
#pragma unroll
    for (int i = 0; i < 2; i++)
#pragma unroll
        for (int j = 0; j < 4; j++) wmma::fill_fragment(acc[i][j], 0.0f);

    PREFETCH(0, 0);
    PREFETCH(32, 1);

#pragma unroll
    for (int c = 0; c < 4; c++) {
        if (c == 3)
            asm volatile("cp.async.wait_group 0;" ::: "memory");
        else
            asm volatile("cp.async.wait_group 1;" ::: "memory");
        __syncthreads();

        char* buf = smem + (c & 1) * BUFBY;
        __nv_bfloat16* sAh = (__nv_bfloat16*)buf;
        __nv_bfloat16* sAl = (__nv_bfloat16*)(buf + ABY);
        __nv_bfloat16* sBh = (__nv_bfloat16*)(buf + 2 * ABY);
        __nv_bfloat16* sBl = (__nv_bfloat16*)(buf + 2 * ABY + BBY);

#pragma unroll
        for (int kk = 0; kk < 32; kk += 16) {
            wmma::fragment<wmma::matrix_a, 16, 16, 16, __nv_bfloat16, wmma::row_major> ah[2], al[2];
#pragma unroll
            for (int m2 = 0; m2 < 2; m2++) {
                wmma::load_matrix_sync(ah[m2], &sAh[(wm * 32 + m2 * 16) * AS + kk], AS);
                wmma::load_matrix_sync(al[m2], &sAl[(wm * 32 + m2 * 16) * AS + kk], AS);
            }
#pragma unroll
            for (int n = 0; n < 4; n++) {
                wmma::fragment<wmma::matrix_b, 16, 16, 16, __nv_bfloat16, wmma::row_major> bh, bl;
                wmma::load_matrix_sync(bh, &sBh[kk * BS + wn * 64 + n * 16], BS);
                wmma::load_matrix_sync(bl, &sBl[kk * BS + wn * 64 + n * 16], BS);
#pragma unroll
                for (int m2 = 0; m2 < 2; m2++) {
                    wmma::mma_sync(acc[m2][n], ah[m2], bh, acc[m2][n]);
                    wmma::mma_sync(acc[m2][n], ah[m2], bl, acc[m2][n]);
                    wmma::mma_sync(acc[m2][n], al[m2], bh, acc[m2][n]);
                }
            }
        }
        __syncthreads();
        if (c < 2) PREFETCH((c + 2) * 32, c & 1);
    }
#undef PREFETCH

    if (bias == nullptr) {
#pragma unroll
        for (int m2 = 0; m2 < 2; m2++)
#pragma unroll
            for (int n = 0; n < 4; n++) {
                int gr = row0 + wm * 32 + m2 * 16;
                int gc = wn * 64 + n * 16;
                wmma::store_matrix_sync(&O[(size_t)gr * 128 + gc], acc[m2][n], 128, wmma::mem_row_major);
            }
    } else {
        // epilogue via smem: add bias, guarded stores
        float* S = (float*)smem;
#pragma unroll
        for (int m2 = 0; m2 < 2; m2++)
#pragma unroll
            for (int n = 0; n < 4; n++)
                wmma::store_matrix_sync(&S[(wm * 32 + m2 * 16) * 128 + wn * 64 + n * 16],
                                        acc[m2][n], 128, wmma::mem_row_major);
        __syncthreads();
        int r = t >> 1;                    // 0..127
        int cbase = (t & 1) * 64;
        int gr = row0 + r;
        if (gr < Mlimit) {
#pragma unroll
            for (int j = 0; j < 16; j++) {
                int c = cbase + j * 4;
                float4 v = *(float4*)&S[r * 128 + c];
                v.x += bias[c + 0];
                v.y += bias[c + 1];
                v.z += bias[c + 2];
                v.w += bias[c + 3];
                *(float4*)&O[(size_t)gr * 128 + c] = v;
            }
        }
    }
}

// ---------------- fused GATv2: warp per node, float4 per lane, 4-edge pipelined ----------------
__global__ void __launch_bounds__(256) gat_warp_k(
    const float* __restrict__ xl, const float* __restrict__ xr,
    const float* __restrict__ xres, const float* __restrict__ bias,
    const float* __restrict__ att, float* __restrict__ out)
{
    int warp = threadIdx.x >> 5;
    int lane = threadIdx.x & 31;
    int v = blockIdx.x * 8 + warp;          // 6250 * 8 == 50000, exact
    int c4 = lane * 4;

    float4 xrv = *(const float4*)&xr[(size_t)v * DD + c4];
    float4 a4  = *(const float4*)&att[c4];

    float denom = 0.f;
    float4 acc = make_float4(0.f, 0.f, 0.f, 0.f);

#define GAT_BODY(M) do { \
        float p0 = (M).x + xrv.x; p0 = (p0 > 0.f) ? p0 : SLOPE * p0; \
        float p1 = (M).y + xrv.y; p1 = (p1 > 0.f) ? p1 : SLOPE * p1; \
        float p2 = (M).z + xrv.z; p2 = (p2 > 0.f) ? p2 : SLOPE * p2; \
        float p3 = (M).w + xrv.w; p3 = (p3 > 0.f) ? p3 : SLOPE * p3; \
        float part = fmaf(p0, a4.x, fmaf(p1, a4.y, fmaf(p2, a4.z, p3 * a4.w))); \
        part += __shfl_xor_sync(0xffffffffu, part, 1); \
        part += __shfl_xor_sync(0xffffffffu, part, 2); \
        part += __shfl_xor_sync(0xffffffffu, part, 4); \
        float w = __expf(part); \
        denom += w; \
        acc.x = fmaf(w, (M).x, acc.x); \
        acc.y = fmaf(w, (M).y, acc.y); \
        acc.z = fmaf(w, (M).z, acc.z); \
        acc.w = fmaf(w, (M).w, acc.w); \
    } while (0)

    {   // self loop
        float4 m = *(const float4*)&xl[(size_t)v * DD + c4];
        GAT_BODY(m);
    }

    int j = g_rowptr[v];
    int e2 = g_rowptr[v + 1];
    // 4-edge pipelined: all gathers issued before any compute
    for (; j + 4 <= e2; j += 4) {
        int s0 = g_col[j];
        int s1 = g_col[j + 1];
        int s2 = g_col[j + 2];
        int s3 = g_col[j + 3];
        float4 m0 = *(const float4*)&xl[(size_t)s0 * DD + c4];
        float4 m1 = *(const float4*)&xl[(size_t)s1 * DD + c4];
        float4 m2 = *(const float4*)&xl[(size_t)s2 * DD + c4];
        float4 m3 = *(const float4*)&xl[(size_t)s3 * DD + c4];
        GAT_BODY(m0);
        GAT_BODY(m1);
        GAT_BODY(m2);
        GAT_BODY(m3);
    }
    for (; j < e2; j++) {
        int s0 = g_col[j];
        float4 m0 = *(const float4*)&xl[(size_t)s0 * DD + c4];
        GAT_BODY(m0);
    }
#undef GAT_BODY

    float inv = 1.f / denom;
    float4 b4 = *(const float4*)&bias[c4];
    float4 r4 = *(const float4*)&xres[(size_t)v * DD + c4];
    float4 o;
    o.x = fmaf(acc.x, inv, b4.x + r4.x);
    o.y = fmaf(acc.y, inv, b4.y + r4.y);
    o.z = fmaf(acc.z, inv, b4.z + r4.z);
    o.w = fmaf(acc.w, inv, b4.w + r4.w);
    *(float4*)&out[(size_t)v * DD + c4] = o;
}

// ---------------- BatchNorm: per-block fp32 partials, then reduce ----------------
__global__ void bn_stats_k(const float* __restrict__ x) {
    int t = threadIdx.x;
    int rows = (NN + gridDim.x - 1) / gridDim.x;
    int r0 = blockIdx.x * rows;
    int r1 = min(NN, r0 + rows);
    float s = 0.f, ss = 0.f;
    for (int r = r0; r < r1; r++) {
        float v = x[(size_t)r * DD + t];
        s += v;
        ss = fmaf(v, v, ss);
    }
    g_psum[blockIdx.x * DD + t] = s;
    g_psq[blockIdx.x * DD + t] = ss;
}

__global__ void bn_final_k(const float* __restrict__ gamma, const float* __restrict__ beta) {
    int t = threadIdx.x;
    double s = 0.0, ss = 0.0;
    for (int b = 0; b < BN_BLKS; b++) {
        s += (double)g_psum[b * DD + t];
        ss += (double)g_psq[b * DD + t];
    }
    double mu = s / (double)NN;
    double var = ss / (double)NN - mu * mu;
    float sc = (float)(1.0 / sqrt(var + BN_EPS)) * gamma[t];
    g_bnsc[t] = sc;
    g_bnsh[t] = beta[t] - (float)mu * sc;
}

// ---------------- launch ----------------
extern "C" void kernel_launch(void* const* d_in, const int* in_sizes, int n_in,
                              void* d_out, int out_size)
{
    const float* x     = (const float*)d_in[0];
    const void*  ei    = (const void*)d_in[1];
    const float* Wl    = (const float*)d_in[2];
    const float* Wr    = (const float*)d_in[3];
    const float* att   = (const float*)d_in[4];
    const float* bias  = (const float*)d_in[5];
    const float* Wres  = (const float*)d_in[6];
    const float* gamma = (const float*)d_in[7];
    const float* beta  = (const float*)d_in[8];
    const float* Wout  = (const float*)d_in[9];
    const float* bout  = (const float*)d_in[10];
    float* out = (float*)d_out;

    int E = in_sizes[1] / 2;

    float *xl, *xr, *xres, *h;
    cudaGetSymbolAddress((void**)&xl,   g_xl);
    cudaGetSymbolAddress((void**)&xr,   g_xr);
    cudaGetSymbolAddress((void**)&xres, g_xres);
    cudaGetSymbolAddress((void**)&h,    g_h);

    cudaFuncSetAttribute(gemm_k, cudaFuncAttributeMaxDynamicSharedMemorySize, SMSZ);

    dim3 gg3(3, NP / 128);   // (3, 391)
    dim3 gg1(1, NP / 128);

    // order: gemm_k is the 4th launch (ncu capture window)
    detect_dtype_k<<<1, 32>>>((const unsigned int*)ei);
    zero_cnt_k<<<(NN + 255) / 256, 256>>>();
    aconvw_k<<<ACONV_G + 48, 256>>>(x, Wl, Wr, Wres, 0);
    gemm_k<<<gg3, 256, SMSZ>>>(xl, xr, xres, nullptr, NP);

    // CSR build
    count_k<<<(E + 255) / 256, 256>>>(ei, E);
    int nb = (NN + 511) / 512;
    scan1_k<<<nb, 512>>>();
    scan2_k<<<1, 128>>>(nb);
    scan3_k<<<nb, 512>>>();
    fill_k<<<(E + 255) / 256, 256>>>(ei, E);

    for (int i = 0; i < LL; i++) {
        if (i > 0) {
            aconvw_k<<<ACONV_G + 48, 256>>>(h, Wl + (size_t)i * DD * DD,
                                            Wr + (size_t)i * DD * DD,
                                            Wres + (size_t)i * DD * DD, 1);
            gemm_k<<<gg3, 256, SMSZ>>>(xl, xr, xres, nullptr, NP);
        }
        gat_warp_k<<<NN / 8, 256>>>(xl, xr, xres, bias + (size_t)i * DD,
                                    att + (size_t)i * HH * CC, h);
        bn_stats_k<<<BN_BLKS, DD>>>(h);
        bn_final_k<<<1, DD>>>(gamma + (size_t)i * DD, beta + (size_t)i * DD);
    }

    // final linear: fused bias epilogue writes d_out directly (row-guarded)
    aconvw_k<<<ACONV_G + 16, 256>>>(h, Wout, nullptr, nullptr, 1);
    gemm_k<<<gg1, 256, SMSZ>>>(out, nullptr, nullptr, bout, NN);
}